// round 2
// baseline (speedup 1.0000x reference)
#include <cuda_runtime.h>
#include <cstdint>
#include <cstddef>

#define BB 1024
#define TT 1024
#define NN 34
#define BPB 7                      // batches per block (forward)
#define FWD_THREADS (BPB * NN)     // 238
#define FWD_BLOCKS  148            // one block per SM

// Score history: row r of batch b holds S_{r-1} (row 0 = init). [B][T+1][N]
__device__ float g_S[(size_t)BB * (TT + 1) * NN];
__device__ int g_idx[BB];

__device__ __forceinline__ unsigned long long addx2(unsigned long long a, unsigned long long b) {
    unsigned long long r;
    asm("add.rn.f32x2 %0, %1, %2;" : "=l"(r) : "l"(a), "l"(b));
    return r;
}
__device__ __forceinline__ unsigned long long packff(float f) {
    unsigned long long r; unsigned u = __float_as_uint(f);
    asm("mov.b64 %0, {%1, %1};" : "=l"(r) : "r"(u));
    return r;
}
__device__ __forceinline__ void unpk(unsigned long long v, float& lo, float& hi) {
    unsigned a, b;
    asm("mov.b64 {%0, %1}, %2;" : "=r"(a), "=r"(b) : "l"(v));
    lo = __uint_as_float(a); hi = __uint_as_float(b);
}

__global__ __launch_bounds__(FWD_THREADS)
void viterbi_fwd(const float* __restrict__ feat,
                 const float* __restrict__ trans,
                 float* __restrict__ out)
{
    const int tid = threadIdx.x;
    const int bl  = tid / NN;
    const int j   = tid % NN;
    int b = blockIdx.x * BPB + bl;
    if (b >= BB) b = BB - 1;       // duplicated batch: identical writes, benign

    __shared__ __align__(16) float sc[2][BPB][36];
    __shared__ float tend[NN];
    __shared__ float fin[BPB][NN];

    // transition row j, packed into f32x2 pairs
    unsigned long long trp[17];
#pragma unroll
    for (int i = 0; i < 17; i++) {
        unsigned lo = __float_as_uint(trans[j * NN + 2 * i]);
        unsigned hi = __float_as_uint(trans[j * NN + 2 * i + 1]);
        asm("mov.b64 %0, {%1, %2};" : "=l"(trp[i]) : "r"(lo), "r"(hi));
    }
    if (tid < NN) tend[tid] = trans[(NN - 1) * NN + tid];

    const float init = (j == NN - 2) ? 0.0f : -6969.0f;
    sc[0][bl][j] = init;
    g_S[((size_t)b * (TT + 1)) * NN + j] = init;   // row 0 = S_{-1}
    __syncthreads();

    const size_t fbase = (size_t)b * ((size_t)TT * NN) + j;
    float f = __ldg(feat + fbase);
    const float* fp = feat + fbase + NN;
    float* sp_out = g_S + ((size_t)b * (TT + 1) + 1) * NN + j;

    int cur = 0;
#pragma unroll 1
    for (int t = 0; t < TT; t++) {
        float fn = 0.0f;
        if (t < TT - 1) fn = __ldg(fp);
        fp += NN;

        const unsigned long long* sp = (const unsigned long long*)&sc[cur][bl][0];
        unsigned long long ff = packff(f);

        float m[NN];
#pragma unroll
        for (int i = 0; i < 17; i++) {
            // (s + f) + tr  — XLA association, two IEEE adds per lane of the pair
            unsigned long long v = addx2(addx2(sp[i], ff), trp[i]);
            unpk(v, m[2 * i], m[2 * i + 1]);
        }
        // exact max tree (FMNMX, no predicates)
#pragma unroll
        for (int s = 1; s < NN; s <<= 1)
#pragma unroll
            for (int k = 0; k + s < NN; k += (s << 1))
                m[k] = fmaxf(m[k], m[k + s]);

        sc[cur ^ 1][bl][j] = m[0];
        *sp_out = m[0];               // S_t[j] history
        sp_out += NN;
        f = fn;
        cur ^= 1;
        __syncthreads();
    }

    fin[bl][j] = sc[cur][bl][j] + tend[j];
    __syncthreads();
    if (j == 0) {
        float bm = -3.4e38f; int bi = 0;
#pragma unroll
        for (int k = 0; k < NN; k++) {
            float v = fin[bl][k];
            if (v > bm) { bm = v; bi = k; }
        }
        out[b] = bm;
        g_idx[b] = bi;
    }
}

// monotone float->orderable-int (no NaNs in data)
__device__ __forceinline__ int fkey(float v) {
    int i = __float_as_int(v);
    return i >= 0 ? i : (i ^ 0x7fffffff);
}

// warp per batch; lane l (<17) owns candidates k=2l, 2l+1 (monotone -> exact ties)
__global__ __launch_bounds__(256)
void viterbi_back(const float* __restrict__ feat,
                  const float* __restrict__ trans,
                  float* __restrict__ out)
{
    __shared__ float tr[NN * NN];
    for (int i = threadIdx.x; i < NN * NN; i += blockDim.x) tr[i] = trans[i];
    __syncthreads();

    const int b = blockIdx.x * 8 + (threadIdx.x >> 5);
    const int l = threadIdx.x & 31;
    const unsigned FULL = 0xffffffffu;

    int j = g_idx[b];
    float* path = out + BB + (size_t)b * (TT + 1);
    if (l == 0) path[TT] = (float)j;

    const float* Sbase = g_S + (size_t)b * (TT + 1) * NN;
    const float* Fbase = feat + (size_t)b * TT * NN;

    float2 Sv[4]; float Fa[4], Fb[4];
#pragma unroll
    for (int u = 0; u < 4; u++) {
        const int s = 3 - u;               // t = 1023-u, t&3 = 3-u
        int t = TT - 1 - u;
        const float* Srow = Sbase + (size_t)t * NN;   // S_{t-1}
        const float* Frow = Fbase + (size_t)t * NN;
        Sv[s] = (l < 17) ? *(const float2*)(Srow + 2 * l) : make_float2(0.f, 0.f);
        Fa[s] = __ldg(Frow + l);
        Fb[s] = (l < 2) ? __ldg(Frow + 32 + l) : 0.f;
    }

#pragma unroll 1
    for (int tb = TT - 1; tb >= 0; tb -= 4) {
#pragma unroll
        for (int u = 0; u < 4; u++) {
            const int s = 3 - u;
            int t = tb - u;

            // broadcast feat[t][j]
            float f1 = __shfl_sync(FULL, Fa[s], j & 31);
            float f2 = __shfl_sync(FULL, Fb[s], j & 1);
            float f  = (j < 32) ? f1 : f2;

            float lv = -3.4e38f; int li = 0; int key = (int)0x80000000;
            if (l < 17) {
                float2 tv = *(const float2*)(tr + j * NN + 2 * l);
                float c0 = (Sv[s].x + f) + tv.x;
                float c1 = (Sv[s].y + f) + tv.y;
                bool p = c0 >= c1;                 // keep lower k on tie
                lv = p ? c0 : c1;
                li = p ? 2 * l : 2 * l + 1;
                key = fkey(lv);
            }
            int M = __reduce_max_sync(FULL, key);
            unsigned msk = __ballot_sync(FULL, key == M);
            int w = __ffs(msk) - 1;                // smallest lane = smallest k
            j = __shfl_sync(FULL, li, w);
            if (l == 0) path[t] = (float)j;

            // refill slot s with rows for t-4
            int tp = t - 4; int tc = tp < 0 ? 0 : tp;
            const float* Srow = Sbase + (size_t)tc * NN;
            const float* Frow = Fbase + (size_t)tc * NN;
            Sv[s] = (l < 17) ? *(const float2*)(Srow + 2 * l) : make_float2(0.f, 0.f);
            Fa[s] = __ldg(Frow + l);
            Fb[s] = (l < 2) ? __ldg(Frow + 32 + l) : 0.f;
        }
    }
}

extern "C" void kernel_launch(void* const* d_in, const int* in_sizes, int n_in,
                              void* d_out, int out_size)
{
    const float* feat  = (const float*)d_in[0];
    const float* trans = (const float*)d_in[1];
    if (n_in >= 2 && in_sizes[0] == NN * NN) {
        feat  = (const float*)d_in[1];
        trans = (const float*)d_in[0];
    }
    float* out = (float*)d_out;

    viterbi_fwd<<<FWD_BLOCKS, FWD_THREADS>>>(feat, trans, out);
    viterbi_back<<<BB / 8, 256>>>(feat, trans, out);
}

// round 3
// speedup vs baseline: 1.8063x; 1.8063x over previous
#include <cuda_runtime.h>
#include <cstdint>
#include <cstddef>

#define BB 1024
#define TT 1024
#define NN 34
#define BPB 4                      // batches per block (forward)
#define FWD_THREADS (BPB * NN)     // 136 threads = 4.25 warps
#define FWD_BLOCKS  296            // exactly 2 CTAs per SM (148*2)

// Score history: row r of batch b holds S_{r-1} (row 0 = init). [B][T+1][N]
__device__ float g_S[(size_t)BB * (TT + 1) * NN];
__device__ int g_idx[BB];

__device__ __forceinline__ unsigned long long addx2(unsigned long long a, unsigned long long b) {
    unsigned long long r;
    asm("add.rn.f32x2 %0, %1, %2;" : "=l"(r) : "l"(a), "l"(b));
    return r;
}
__device__ __forceinline__ unsigned long long packff(float f) {
    unsigned long long r; unsigned u = __float_as_uint(f);
    asm("mov.b64 %0, {%1, %1};" : "=l"(r) : "r"(u));
    return r;
}
__device__ __forceinline__ void unpk(unsigned long long v, float& lo, float& hi) {
    unsigned a, b;
    asm("mov.b64 {%0, %1}, %2;" : "=r"(a), "=r"(b) : "l"(v));
    lo = __uint_as_float(a); hi = __uint_as_float(b);
}

__global__ __launch_bounds__(FWD_THREADS)
void viterbi_fwd(const float* __restrict__ feat,
                 const float* __restrict__ trans,
                 float* __restrict__ out)
{
    const int tid = threadIdx.x;
    const int bl  = tid / NN;
    const int j   = tid % NN;
    int b = blockIdx.x * BPB + bl;
    if (b >= BB) b = BB - 1;       // tail blocks duplicate batch 1023: identical writes, benign

    __shared__ __align__(16) float sc[2][BPB][36];
    __shared__ float tend[NN];
    __shared__ float fin[BPB][NN];

    // transition row j packed in f32x2 pairs
    unsigned long long trp[17];
#pragma unroll
    for (int i = 0; i < 17; i++) {
        unsigned lo = __float_as_uint(trans[j * NN + 2 * i]);
        unsigned hi = __float_as_uint(trans[j * NN + 2 * i + 1]);
        asm("mov.b64 %0, {%1, %2};" : "=l"(trp[i]) : "r"(lo), "r"(hi));
    }
    if (tid < NN) tend[tid] = trans[(NN - 1) * NN + tid];

    const float init = (j == NN - 2) ? 0.0f : -6969.0f;
    sc[0][bl][j] = init;
    g_S[((size_t)b * (TT + 1)) * NN + j] = init;
    __syncthreads();

    const size_t fbase = (size_t)b * ((size_t)TT * NN) + j;
    const float* fp = feat + fbase;
    float* sp_out = g_S + ((size_t)b * (TT + 1) + 1) * NN + j;

    // 4-deep feat prefetch ring (MLP=4 hides DRAM latency)
    float fring[4];
#pragma unroll
    for (int u = 0; u < 4; u++) fring[u] = __ldg(fp + (size_t)u * NN);
    fp += (size_t)4 * NN;

    int cur = 0;
#pragma unroll 1
    for (int tb = 0; tb < TT; tb += 4) {
#pragma unroll
        for (int u = 0; u < 4; u++) {
            const int t = tb + u;
            float f = fring[u];
            // refill ring slot early (load for t+4)
            float fn = 0.0f;
            if (t + 4 < TT) fn = __ldg(fp);
            fp += NN;
            fring[u] = fn;

            const ulonglong2* sp2 = (const ulonglong2*)&sc[cur][bl][0];
            unsigned long long ff = packff(f);

            float m[NN];
#pragma unroll
            for (int i = 0; i < 8; i++) {           // 8x LDS.128 = 32 floats
                ulonglong2 q = sp2[i];
                unsigned long long v0 = addx2(addx2(q.x, ff), trp[2 * i]);
                unsigned long long v1 = addx2(addx2(q.y, ff), trp[2 * i + 1]);
                unpk(v0, m[4 * i], m[4 * i + 1]);
                unpk(v1, m[4 * i + 2], m[4 * i + 3]);
            }
            {
                unsigned long long q = *(const unsigned long long*)&sc[cur][bl][32];
                unsigned long long v = addx2(addx2(q, ff), trp[16]);
                unpk(v, m[32], m[33]);
            }
            // exact max tree (FMNMX)
#pragma unroll
            for (int s = 1; s < NN; s <<= 1)
#pragma unroll
                for (int k = 0; k + s < NN; k += (s << 1))
                    m[k] = fmaxf(m[k], m[k + s]);

            sc[cur ^ 1][bl][j] = m[0];
            *sp_out = m[0];
            sp_out += NN;
            cur ^= 1;
            __syncthreads();
        }
    }

    fin[bl][j] = sc[cur][bl][j] + tend[j];
    __syncthreads();
    if (j == 0) {
        float bm = -3.4e38f; int bi = 0;
#pragma unroll
        for (int k = 0; k < NN; k++) {
            float v = fin[bl][k];
            if (v > bm) { bm = v; bi = k; }
        }
        out[b] = bm;
        g_idx[b] = bi;
    }
}

// monotone float -> orderable int (data has no NaN)
__device__ __forceinline__ int fkey(float v) {
    int i = __float_as_int(v);
    return i >= 0 ? i : (i ^ 0x7fffffff);
}

// warp per batch; lane l<17 owns candidates k=2l,2l+1 (monotone lane->k keeps tie order exact)
__global__ __launch_bounds__(256)
void viterbi_back(const float* __restrict__ feat,
                  const float* __restrict__ trans,
                  float* __restrict__ out)
{
    __shared__ float tr[NN * NN];
    for (int i = threadIdx.x; i < NN * NN; i += blockDim.x) tr[i] = trans[i];
    __syncthreads();

    const int b = blockIdx.x * 8 + (threadIdx.x >> 5);
    const int l = threadIdx.x & 31;
    const unsigned FULL = 0xffffffffu;

    int j = g_idx[b];
    float* path = out + BB + (size_t)b * (TT + 1);
    if (l == 0) path[TT] = (float)j;

    const float* Sbase = g_S + (size_t)b * (TT + 1) * NN;
    const float* Fbase = feat + (size_t)b * TT * NN;

    // 4-deep rings: S_{t-1} pair per lane, feat row split Fa (j<32) / Fb (j>=32)
    float2 Sv[4]; float Fa[4], Fb[4];
#pragma unroll
    for (int u = 0; u < 4; u++) {
        const int s = 3 - u;               // slot for t = 1023-u (t&3 == 3-u)
        int t = TT - 1 - u;
        const float* Srow = Sbase + (size_t)t * NN;   // holds S_{t-1}
        const float* Frow = Fbase + (size_t)t * NN;
        Sv[s] = (l < 17) ? *(const float2*)(Srow + 2 * l) : make_float2(0.f, 0.f);
        Fa[s] = __ldg(Frow + l);
        Fb[s] = __ldg(Frow + 32 + (l & 1));
    }

#pragma unroll 1
    for (int tb = TT - 1; tb >= 0; tb -= 4) {
#pragma unroll
        for (int u = 0; u < 4; u++) {
            const int s = 3 - u;
            int t = tb - u;

            // f = feat[t][j] : one pair of independent shfls + select
            float f1 = __shfl_sync(FULL, Fa[s], j & 31);
            float f2 = __shfl_sync(FULL, Fb[s], j & 1);
            float f  = (j < 32) ? f1 : f2;

            int key = (int)0x80000000; int li = 0;
            if (l < 17) {
                float2 tv = *(const float2*)(tr + j * NN + 2 * l);
                float c0 = (Sv[s].x + f) + tv.x;     // XLA association
                float c1 = (Sv[s].y + f) + tv.y;
                bool p = c0 >= c1;                    // keep lower k on tie
                float lv = p ? c0 : c1;
                li = p ? 2 * l : 2 * l + 1;
                key = fkey(lv);
            }
            int M  = __reduce_max_sync(FULL, key);
            int r2 = __reduce_max_sync(FULL, (key == M) ? (63 - li) : 0);
            j = 63 - r2;                              // smallest k among maxima
            if (l == 0) path[t] = (float)j;

            // refill slot s with rows for t-4 (addresses path-independent)
            int tp = t - 4; int tc = tp < 0 ? 0 : tp;
            const float* Srow = Sbase + (size_t)tc * NN;
            const float* Frow = Fbase + (size_t)tc * NN;
            Sv[s] = (l < 17) ? *(const float2*)(Srow + 2 * l) : make_float2(0.f, 0.f);
            Fa[s] = __ldg(Frow + l);
            Fb[s] = __ldg(Frow + 32 + (l & 1));
        }
    }
}

extern "C" void kernel_launch(void* const* d_in, const int* in_sizes, int n_in,
                              void* d_out, int out_size)
{
    const float* feat  = (const float*)d_in[0];
    const float* trans = (const float*)d_in[1];
    if (n_in >= 2 && in_sizes[0] == NN * NN) {
        feat  = (const float*)d_in[1];
        trans = (const float*)d_in[0];
    }
    float* out = (float*)d_out;

    viterbi_fwd<<<FWD_BLOCKS, FWD_THREADS>>>(feat, trans, out);
    viterbi_back<<<BB / 8, 256>>>(feat, trans, out);
}